// round 4
// baseline (speedup 1.0000x reference)
#include <cuda_runtime.h>
#include <cuda_bf16.h>
#include <cstdint>

// Live computation: out[B*S, E] = x @ Wout + bout   (attention in reference is dead code)
// M=8192, N=512, K=512, fp32 in/out.
// bf16 3-term split: out = x_hi@W_hi + x_lo@W_hi + x_hi@W_lo  (lo*lo dropped, ~2^-18 rel)
#define MM 8192
#define NN 512
#define KK 512
#define KA 1024      // A' = [x_hi | x_lo]
#define KB 1536      // B' = [W_hi | W_hi | W_lo]
#define TM 128
#define TN 128
#define TK 64
#define NCHUNK (KB / TK)   // 24

// Scratch (device globals: allocation-free contract)
__device__ __align__(16) __nv_bfloat16 g_A[(size_t)MM * KA];   // 16 MB  [m][k']
__device__ __align__(16) __nv_bfloat16 g_B[(size_t)NN * KB];   // 1.5 MB [n][k']

// ---------------------------------------------------------------------------
// Helpers (sm_100 baseline only: cp.async / ldmatrix / mma.sync)
// ---------------------------------------------------------------------------
__device__ __forceinline__ uint32_t smem_u32(const void* p) {
    uint32_t r;
    asm("{ .reg .u64 t; cvta.to.shared.u64 t, %1; cvt.u32.u64 %0, t; }" : "=r"(r) : "l"(p));
    return r;
}
__device__ __forceinline__ uint32_t sw128(uint32_t off) { return off ^ ((off >> 3) & 0x70); }

__device__ __forceinline__ void cp16(uint32_t dst, const void* src) {
    asm volatile("cp.async.cg.shared.global [%0], [%1], 16;" :: "r"(dst), "l"(src) : "memory");
}
__device__ __forceinline__ void cp_commit() {
    asm volatile("cp.async.commit_group;" ::: "memory");
}
__device__ __forceinline__ void cp_wait1() {
    asm volatile("cp.async.wait_group 1;" ::: "memory");
}
__device__ __forceinline__ void ldsm_x4(uint32_t* r, uint32_t addr) {
    asm volatile("ldmatrix.sync.aligned.m8n8.x4.shared.b16 {%0,%1,%2,%3}, [%4];"
                 : "=r"(r[0]), "=r"(r[1]), "=r"(r[2]), "=r"(r[3]) : "r"(addr));
}
__device__ __forceinline__ void mma16816(float* c, const uint32_t* a, uint32_t b0, uint32_t b1) {
    asm volatile(
        "mma.sync.aligned.m16n8k16.row.col.f32.bf16.bf16.f32 "
        "{%0,%1,%2,%3}, {%4,%5,%6,%7}, {%8,%9}, {%0,%1,%2,%3};"
        : "+f"(c[0]), "+f"(c[1]), "+f"(c[2]), "+f"(c[3])
        : "r"(a[0]), "r"(a[1]), "r"(a[2]), "r"(a[3]), "r"(b0), "r"(b1));
}

// ---------------------------------------------------------------------------
// Prep: fp32 -> split bf16
// ---------------------------------------------------------------------------
__device__ __forceinline__ uint32_t pack2(__nv_bfloat16 a, __nv_bfloat16 b) {
    return (uint32_t)__bfloat16_as_ushort(a) | ((uint32_t)__bfloat16_as_ushort(b) << 16);
}

__global__ void __launch_bounds__(256) prep_x(const float* __restrict__ x) {
    int idx = blockIdx.x * 256 + threadIdx.x;        // over float4: MM*KK/4
    int m = idx >> 7;                                // KK/4 = 128
    int k = (idx & 127) << 2;
    float4 v = reinterpret_cast<const float4*>(x)[idx];
    float f[4] = {v.x, v.y, v.z, v.w};
    __nv_bfloat16 hi[4], lo[4];
#pragma unroll
    for (int i = 0; i < 4; ++i) {
        hi[i] = __float2bfloat16(f[i]);
        lo[i] = __float2bfloat16(f[i] - __bfloat162float(hi[i]));
    }
    uint2 whi = make_uint2(pack2(hi[0], hi[1]), pack2(hi[2], hi[3]));
    uint2 wlo = make_uint2(pack2(lo[0], lo[1]), pack2(lo[2], lo[3]));
    size_t base = (size_t)m * KA + k;
    *reinterpret_cast<uint2*>(&g_A[base])       = whi;
    *reinterpret_cast<uint2*>(&g_A[base + 512]) = wlo;
}

__global__ void __launch_bounds__(256) prep_w(const float* __restrict__ W) {
    int idx = blockIdx.x * 256 + threadIdx.x;        // over NN*KK/4
    int n = idx >> 7;
    int k = (idx & 127) << 2;
    __nv_bfloat16 hi[4], lo[4];
#pragma unroll
    for (int i = 0; i < 4; ++i) {
        float w = W[(size_t)(k + i) * NN + n];       // W[k][n] -> B'[n][k] (transpose)
        hi[i] = __float2bfloat16(w);
        lo[i] = __float2bfloat16(w - __bfloat162float(hi[i]));
    }
    uint2 whi = make_uint2(pack2(hi[0], hi[1]), pack2(hi[2], hi[3]));
    uint2 wlo = make_uint2(pack2(lo[0], lo[1]), pack2(lo[2], lo[3]));
    size_t base = (size_t)n * KB + k;
    *reinterpret_cast<uint2*>(&g_B[base])        = whi;
    *reinterpret_cast<uint2*>(&g_B[base + 512])  = whi;
    *reinterpret_cast<uint2*>(&g_B[base + 1024]) = wlo;
}

// ---------------------------------------------------------------------------
// GEMM: 128x128 CTA tile, 8 warps (4m x 2n -> 32x64 warp tile),
// cp.async double buffer, ldmatrix + mma.sync.m16n8k16 bf16, fp32 accum.
// SMEM: [0,512) bias f32; [512, 512+2*32768) = {A(16K)+B(16K)} x 2 buffers.
// ---------------------------------------------------------------------------
#define SM_BIAS 0
#define SM_TILE 512
#define SMEM_BYTES (512 + 2 * 32768)

__global__ void __launch_bounds__(256) gemm_kernel(const float* __restrict__ bout,
                                                   float* __restrict__ out) {
    extern __shared__ char smem[];
    const uint32_t sb = smem_u32(smem);
    const int tid = threadIdx.x;
    const int lane = tid & 31;
    const int wid = tid >> 5;
    const int warp_m = wid >> 1;       // 0..3
    const int warp_n = wid & 1;        // 0..1
    const int m_blk = blockIdx.x >> 2, n_blk = blockIdx.x & 3;
    const int m_base = m_blk * TM, n_base = n_blk * TN;

    if (tid < TN) reinterpret_cast<float*>(smem + SM_BIAS)[tid] = bout[n_base + tid];

    // ---- async prefetch of one 64-k chunk into buffer (kb&1) ----
    auto prefetch = [&](int kb) {
        const int ka = (kb < 16) ? kb : (kb - 16);   // chunks 16..23 reuse x_hi
        const uint32_t sa = sb + SM_TILE + (kb & 1) * 32768;
#pragma unroll
        for (int r = 0; r < 4; ++r) {
            int idx = tid + (r << 8);                // 0..1023
            int row = idx >> 3, c16 = idx & 7;
            uint32_t sw = sw128((uint32_t)(row * 128 + c16 * 16));
            cp16(sa + sw,         g_A + (size_t)(m_base + row) * KA + ka * TK + c16 * 8);
            cp16(sa + 16384 + sw, g_B + (size_t)(n_base + row) * KB + kb * TK + c16 * 8);
        }
    };

    prefetch(0); cp_commit();
    prefetch(1); cp_commit();

    float c[2][8][4];
#pragma unroll
    for (int mi = 0; mi < 2; ++mi)
#pragma unroll
        for (int ni = 0; ni < 8; ++ni)
#pragma unroll
            for (int q = 0; q < 4; ++q) c[mi][ni][q] = 0.f;

    for (int kb = 0; kb < NCHUNK; ++kb) {
        cp_wait1();
        __syncthreads();
        const uint32_t sa  = sb + SM_TILE + (kb & 1) * 32768;
        const uint32_t sbb = sa + 16384;
#pragma unroll
        for (int s = 0; s < 4; ++s) {                // 4 k16 steps in the 64-chunk
            uint32_t a[2][4];
#pragma unroll
            for (int mi = 0; mi < 2; ++mi) {
                int row = warp_m * 32 + mi * 16 + (lane & 15);
                int kbyte = s * 32 + ((lane >> 4) << 4);
                ldsm_x4(a[mi], sa + sw128((uint32_t)(row * 128 + kbyte)));
            }
#pragma unroll
            for (int p = 0; p < 4; ++p) {            // n-pairs: covers n8 tiles 2p, 2p+1
                uint32_t b[4];
                int nrow = warp_n * 64 + p * 16 + ((lane >> 4) * 8 + (lane & 7));
                int kbyte = s * 32 + (((lane >> 3) & 1) << 4);
                ldsm_x4(b, sbb + sw128((uint32_t)(nrow * 128 + kbyte)));
                mma16816(c[0][2 * p],     a[0], b[0], b[1]);
                mma16816(c[0][2 * p + 1], a[0], b[2], b[3]);
                mma16816(c[1][2 * p],     a[1], b[0], b[1]);
                mma16816(c[1][2 * p + 1], a[1], b[2], b[3]);
            }
        }
        __syncthreads();
        if (kb + 2 < NCHUNK) prefetch(kb + 2);
        cp_commit();                                 // empty group near tail keeps counts right
    }

    // ---- epilogue: + bias, fp32 stores ----
    const float* bias = reinterpret_cast<const float*>(smem + SM_BIAS);
#pragma unroll
    for (int mi = 0; mi < 2; ++mi) {
        int gm0 = m_base + warp_m * 32 + mi * 16 + (lane >> 2);
#pragma unroll
        for (int ni = 0; ni < 8; ++ni) {
            int cn = warp_n * 64 + ni * 8 + ((lane & 3) << 1);
            int gn = n_base + cn;
            float b0 = bias[cn], b1 = bias[cn + 1];
            float2 v0 = make_float2(c[mi][ni][0] + b0, c[mi][ni][1] + b1);
            float2 v1 = make_float2(c[mi][ni][2] + b0, c[mi][ni][3] + b1);
            *reinterpret_cast<float2*>(out + (size_t)gm0 * NN + gn)       = v0;
            *reinterpret_cast<float2*>(out + (size_t)(gm0 + 8) * NN + gn) = v1;
        }
    }
}

// ---------------------------------------------------------------------------
// kernel_launch
// inputs: 0=x (fp32 4*2048*512), 1=attn_mask (dead), 2=Wqkv (dead),
//         3=bqkv (dead), 4=Wout (fp32 512*512), 5=bout (fp32 512)
// ---------------------------------------------------------------------------
extern "C" void kernel_launch(void* const* d_in, const int* in_sizes, int n_in,
                              void* d_out, int out_size) {
    const float* x    = (const float*)d_in[0];
    const float* Wout = (const float*)d_in[4];
    const float* bo   = (const float*)d_in[5];
    float* out = (float*)d_out;

    cudaFuncSetAttribute(gemm_kernel, cudaFuncAttributeMaxDynamicSharedMemorySize, SMEM_BYTES);

    prep_x<<<(MM * KK / 4) / 256, 256>>>(x);
    prep_w<<<(NN * KK / 4) / 256, 256>>>(Wout);
    gemm_kernel<<<(MM / TM) * (NN / TN), 256, SMEM_BYTES>>>(bo, out);
}

// round 5
// speedup vs baseline: 1.2008x; 1.2008x over previous
#include <cuda_runtime.h>
#include <cuda_fp16.h>
#include <cstdint>

// Live computation: out[B*S, E] = x @ Wout + bout  (attention in reference is dead code)
// M=8192, N=512, K=512, fp32 in/out.
// fp16 2-term split on W only: out = x_f @ W_hi + x_f @ W_lo, with
//   W_hi = fp16(W), W_lo = fp16(W - W_hi)  ->  W_hi+W_lo = W to ~2^-22.
// fp16 products are EXACT in the fp32 MMA accumulator, so the only error is
// fp16 rounding of x: ~2.8e-4 RMS relative (<< 1e-3 gate).
#define MM 8192
#define NN 512
#define KK 512
#define KB2 1024     // B' = [W_hi | W_lo], n-major rows
#define TM 128
#define TN 128

// W split scratch (device global: allocation-free contract). 1 MB.
__device__ __align__(16) __half g_B[(size_t)NN * KB2];

// ---------------------------------------------------------------------------
// Helpers (baseline sm_100: cp.async / ldmatrix / mma.sync)
// ---------------------------------------------------------------------------
__device__ __forceinline__ uint32_t smem_u32(const void* p) {
    uint32_t r;
    asm("{ .reg .u64 t; cvta.to.shared.u64 t, %1; cvt.u32.u64 %0, t; }" : "=r"(r) : "l"(p));
    return r;
}
__device__ __forceinline__ uint32_t sw128(uint32_t off) { return off ^ ((off >> 3) & 0x70); }

__device__ __forceinline__ void cp16(uint32_t dst, const void* src) {
    asm volatile("cp.async.cg.shared.global [%0], [%1], 16;" :: "r"(dst), "l"(src) : "memory");
}
__device__ __forceinline__ void cp_commit() {
    asm volatile("cp.async.commit_group;" ::: "memory");
}
__device__ __forceinline__ void cp_wait1() {
    asm volatile("cp.async.wait_group 1;" ::: "memory");
}
__device__ __forceinline__ void ldsm_x4(uint32_t* r, uint32_t addr) {
    asm volatile("ldmatrix.sync.aligned.m8n8.x4.shared.b16 {%0,%1,%2,%3}, [%4];"
                 : "=r"(r[0]), "=r"(r[1]), "=r"(r[2]), "=r"(r[3]) : "r"(addr));
}
__device__ __forceinline__ void mma16816(float* c, const uint32_t* a, uint32_t b0, uint32_t b1) {
    asm volatile(
        "mma.sync.aligned.m16n8k16.row.col.f32.f16.f16.f32 "
        "{%0,%1,%2,%3}, {%4,%5,%6,%7}, {%8,%9}, {%0,%1,%2,%3};"
        : "+f"(c[0]), "+f"(c[1]), "+f"(c[2]), "+f"(c[3])
        : "r"(a[0]), "r"(a[1]), "r"(a[2]), "r"(a[3]), "r"(b0), "r"(b1));
}

// ---------------------------------------------------------------------------
// prep_w: W[k][n] fp32 -> g_B[n][0..511]=fp16(W), g_B[n][512..1023]=fp16(W-hi)
// ---------------------------------------------------------------------------
__global__ void __launch_bounds__(256) prep_w(const float* __restrict__ W) {
    int idx = blockIdx.x * 256 + threadIdx.x;        // over NN*KK/4
    int n = idx >> 7;
    int k = (idx & 127) << 2;
    __half hi[4], lo[4];
#pragma unroll
    for (int i = 0; i < 4; ++i) {
        float w = W[(size_t)(k + i) * NN + n];       // transpose to n-major
        hi[i] = __float2half_rn(w);
        lo[i] = __float2half_rn(w - __half2float(hi[i]));
    }
    uint2 uhi, ulo;
    uhi.x = (uint32_t)__half_as_ushort(hi[0]) | ((uint32_t)__half_as_ushort(hi[1]) << 16);
    uhi.y = (uint32_t)__half_as_ushort(hi[2]) | ((uint32_t)__half_as_ushort(hi[3]) << 16);
    ulo.x = (uint32_t)__half_as_ushort(lo[0]) | ((uint32_t)__half_as_ushort(lo[1]) << 16);
    ulo.y = (uint32_t)__half_as_ushort(lo[2]) | ((uint32_t)__half_as_ushort(lo[3]) << 16);
    size_t base = (size_t)n * KB2 + k;
    *reinterpret_cast<uint2*>(&g_B[base])       = uhi;
    *reinterpret_cast<uint2*>(&g_B[base + 512]) = ulo;
}

// ---------------------------------------------------------------------------
// Fused GEMM: 128x128 CTA tile, 8 warps (4m x 2n), 8 k64 fp32 chunks.
// Per chunk: LDG fp32 x -> cvt fp16 -> STS (double buffered);
//            cp.async W_hi+W_lo sub-tiles (double buffered);
//            MMA 2 terms x 4 k16-steps, A fragments shared across terms.
// SMEM: [0,512) bias; [512, 512+2*16K) A bufs; [then 2*32K) B bufs = 98816 B.
// ---------------------------------------------------------------------------
#define SM_BIAS 0
#define SM_A 512
#define SM_B (512 + 2 * 16384)
#define SMEM_BYTES (512 + 2 * 16384 + 2 * 32768)

__global__ void __launch_bounds__(256, 2) gemm_kernel(const float* __restrict__ x,
                                                      const float* __restrict__ bout,
                                                      float* __restrict__ out) {
    extern __shared__ char smem[];
    const uint32_t sb = smem_u32(smem);
    const int tid = threadIdx.x;
    const int lane = tid & 31;
    const int wid = tid >> 5;
    const int warp_m = wid >> 1;       // 0..3
    const int warp_n = wid & 1;        // 0..1
    const int m_blk = blockIdx.x >> 2, n_blk = blockIdx.x & 3;
    const int m_base = m_blk * TM, n_base = n_blk * TN;

    if (tid < TN) reinterpret_cast<float*>(smem + SM_BIAS)[tid] = bout[n_base + tid];

    const float* gx = x + (size_t)m_base * KK;

    // ---- load one 128x64 fp32 x chunk into regs (8 float4 / thread) ----
    uint4 xr[8];
    auto ldx = [&](int kb) {
#pragma unroll
        for (int r = 0; r < 8; ++r) {
            int idx = tid + (r << 8);
            int row = idx >> 4, c4 = idx & 15;
            xr[r] = *reinterpret_cast<const uint4*>(gx + (size_t)row * KK + kb * 64 + c4 * 4);
        }
    };
    // ---- convert + store chunk into A buffer s ----
    auto stsA = [&](int s) {
        const uint32_t sa = sb + SM_A + s * 16384;
#pragma unroll
        for (int r = 0; r < 8; ++r) {
            int idx = tid + (r << 8);
            int row = idx >> 4, c4 = idx & 15;
            __half2 h0 = __floats2half2_rn(__uint_as_float(xr[r].x), __uint_as_float(xr[r].y));
            __half2 h1 = __floats2half2_rn(__uint_as_float(xr[r].z), __uint_as_float(xr[r].w));
            uint32_t u0 = *reinterpret_cast<uint32_t*>(&h0);
            uint32_t u1 = *reinterpret_cast<uint32_t*>(&h1);
            uint32_t off = sw128((uint32_t)(row * 128 + c4 * 8));
            asm volatile("st.shared.v2.b32 [%0], {%1,%2};"
                         :: "r"(sa + off), "r"(u0), "r"(u1) : "memory");
        }
    };
    // ---- cp.async W_hi + W_lo sub-tiles for chunk kb into B buffer kb&1 ----
    auto prefB = [&](int kb) {
        const uint32_t sbb = sb + SM_B + (kb & 1) * 32768;
#pragma unroll
        for (int r = 0; r < 8; ++r) {
            int idx = tid + ((r & 3) << 8);          // 0..1023
            int row = idx >> 3, c16 = idx & 7;
            int t = r >> 2;                          // 0=hi, 1=lo
            uint32_t sw = sw128((uint32_t)(row * 128 + c16 * 16));
            cp16(sbb + t * 16384 + sw,
                 g_B + (size_t)(n_base + row) * KB2 + t * 512 + kb * 64 + c16 * 8);
        }
    };

    ldx(0);
    prefB(0); cp_commit();
    prefB(1); cp_commit();

    float c[2][8][4];
#pragma unroll
    for (int mi = 0; mi < 2; ++mi)
#pragma unroll
        for (int ni = 0; ni < 8; ++ni)
#pragma unroll
            for (int q = 0; q < 4; ++q) c[mi][ni][q] = 0.f;

    for (int kb = 0; kb < 8; ++kb) {
        stsA(kb & 1);                 // writes bufA[kb&1]; last read at chunk kb-2, fenced by kb-1's sync
        cp_wait1();                   // B chunk kb resident
        __syncthreads();
        if (kb < 7) ldx(kb + 1);      // overlap next x load with MMA

        const uint32_t sa  = sb + SM_A + (kb & 1) * 16384;
        const uint32_t sbb = sb + SM_B + (kb & 1) * 32768;
#pragma unroll
        for (int s = 0; s < 4; ++s) {                // k16 steps
            uint32_t a[2][4];
#pragma unroll
            for (int mi = 0; mi < 2; ++mi) {
                int row = warp_m * 32 + mi * 16 + (lane & 15);
                int kbyte = s * 32 + ((lane >> 4) << 4);
                ldsm_x4(a[mi], sa + sw128((uint32_t)(row * 128 + kbyte)));
            }
#pragma unroll
            for (int t = 0; t < 2; ++t) {            // W_hi then W_lo, same A frags
                const uint32_t sbt = sbb + t * 16384;
#pragma unroll
                for (int p = 0; p < 4; ++p) {
                    uint32_t b[4];
                    int nrow = warp_n * 64 + p * 16 + ((lane >> 4) * 8 + (lane & 7));
                    int kbyte = s * 32 + (((lane >> 3) & 1) << 4);
                    ldsm_x4(b, sbt + sw128((uint32_t)(nrow * 128 + kbyte)));
                    mma16816(c[0][2 * p],     a[0], b[0], b[1]);
                    mma16816(c[0][2 * p + 1], a[0], b[2], b[3]);
                    mma16816(c[1][2 * p],     a[1], b[0], b[1]);
                    mma16816(c[1][2 * p + 1], a[1], b[2], b[3]);
                }
            }
        }
        __syncthreads();
        if (kb < 6) prefB(kb + 2);
        cp_commit();                  // empty groups near tail keep wait counts valid
    }

    // ---- epilogue: + bias, fp32 stores ----
    const float* bias = reinterpret_cast<const float*>(smem + SM_BIAS);
#pragma unroll
    for (int mi = 0; mi < 2; ++mi) {
        int gm0 = m_base + warp_m * 32 + mi * 16 + (lane >> 2);
#pragma unroll
        for (int ni = 0; ni < 8; ++ni) {
            int cn = warp_n * 64 + ni * 8 + ((lane & 3) << 1);
            int gn = n_base + cn;
            float b0 = bias[cn], b1 = bias[cn + 1];
            float2 v0 = make_float2(c[mi][ni][0] + b0, c[mi][ni][1] + b1);
            float2 v1 = make_float2(c[mi][ni][2] + b0, c[mi][ni][3] + b1);
            *reinterpret_cast<float2*>(out + (size_t)gm0 * NN + gn)       = v0;
            *reinterpret_cast<float2*>(out + (size_t)(gm0 + 8) * NN + gn) = v1;
        }
    }
}

// ---------------------------------------------------------------------------
// kernel_launch
// inputs: 0=x (fp32 4*2048*512), 1=attn_mask (dead), 2=Wqkv (dead),
//         3=bqkv (dead), 4=Wout (fp32 512*512), 5=bout (fp32 512)
// ---------------------------------------------------------------------------
extern "C" void kernel_launch(void* const* d_in, const int* in_sizes, int n_in,
                              void* d_out, int out_size) {
    const float* x    = (const float*)d_in[0];
    const float* Wout = (const float*)d_in[4];
    const float* bo   = (const float*)d_in[5];
    float* out = (float*)d_out;

    cudaFuncSetAttribute(gemm_kernel, cudaFuncAttributeMaxDynamicSharedMemorySize, SMEM_BYTES);

    prep_w<<<(NN * KK / 4) / 256, 256>>>(Wout);
    gemm_kernel<<<(MM / TM) * (NN / TN), 256, SMEM_BYTES>>>(x, bo, out);
}

// round 6
// speedup vs baseline: 1.7154x; 1.4286x over previous
#include <cuda_runtime.h>
#include <cuda_fp16.h>
#include <cstdint>

// Live computation: out[B*S, E] = x @ Wout + bout  (attention in reference is dead code)
// M=8192, N=512, K=512, fp32 in/out.
// Single-term fp16 GEMM: out = fp16(x) @ fp16(W) + bias.
// fp16 products are exact in the fp32 MMA accumulator; error = input rounding only.
// Measured x-rounding contribution (R5): 2.07e-4. Adding W rounding: ~2.9e-4 << 1e-3.
#define MM 8192
#define NN 512
#define KK 512
#define TM 128
#define TN 128

// W_hi scratch (device global: allocation-free contract). 0.5 MB, n-major.
__device__ __align__(16) __half g_B[(size_t)NN * KK];

// ---------------------------------------------------------------------------
// Helpers (baseline sm_100: cp.async / ldmatrix / mma.sync)
// ---------------------------------------------------------------------------
__device__ __forceinline__ uint32_t smem_u32(const void* p) {
    uint32_t r;
    asm("{ .reg .u64 t; cvta.to.shared.u64 t, %1; cvt.u32.u64 %0, t; }" : "=r"(r) : "l"(p));
    return r;
}
__device__ __forceinline__ uint32_t sw128(uint32_t off) { return off ^ ((off >> 3) & 0x70); }

__device__ __forceinline__ void cp16(uint32_t dst, const void* src) {
    asm volatile("cp.async.cg.shared.global [%0], [%1], 16;" :: "r"(dst), "l"(src) : "memory");
}
__device__ __forceinline__ void cp_commit() {
    asm volatile("cp.async.commit_group;" ::: "memory");
}
__device__ __forceinline__ void cp_wait1() {
    asm volatile("cp.async.wait_group 1;" ::: "memory");
}
__device__ __forceinline__ void ldsm_x4(uint32_t* r, uint32_t addr) {
    asm volatile("ldmatrix.sync.aligned.m8n8.x4.shared.b16 {%0,%1,%2,%3}, [%4];"
                 : "=r"(r[0]), "=r"(r[1]), "=r"(r[2]), "=r"(r[3]) : "r"(addr));
}
__device__ __forceinline__ void mma16816(float* c, const uint32_t* a, uint32_t b0, uint32_t b1) {
    asm volatile(
        "mma.sync.aligned.m16n8k16.row.col.f32.f16.f16.f32 "
        "{%0,%1,%2,%3}, {%4,%5,%6,%7}, {%8,%9}, {%0,%1,%2,%3};"
        : "+f"(c[0]), "+f"(c[1]), "+f"(c[2]), "+f"(c[3])
        : "r"(a[0]), "r"(a[1]), "r"(a[2]), "r"(a[3]), "r"(b0), "r"(b1));
}

// ---------------------------------------------------------------------------
// prep_w: W[k][n] fp32 -> g_B[n][k] = fp16(W)  (transposed to n-major)
// ---------------------------------------------------------------------------
__global__ void __launch_bounds__(256) prep_w(const float* __restrict__ W) {
    int idx = blockIdx.x * 256 + threadIdx.x;        // over NN*KK/4
    int n = idx >> 7;
    int k = (idx & 127) << 2;
    __half hi[4];
#pragma unroll
    for (int i = 0; i < 4; ++i)
        hi[i] = __float2half_rn(W[(size_t)(k + i) * NN + n]);
    uint2 uhi;
    uhi.x = (uint32_t)__half_as_ushort(hi[0]) | ((uint32_t)__half_as_ushort(hi[1]) << 16);
    uhi.y = (uint32_t)__half_as_ushort(hi[2]) | ((uint32_t)__half_as_ushort(hi[3]) << 16);
    *reinterpret_cast<uint2*>(&g_B[(size_t)n * KK + k]) = uhi;
}

// ---------------------------------------------------------------------------
// Fused GEMM: 128x128 CTA tile, 8 warps (4m x 2n), 8 k64 chunks.
// Per chunk: LDG fp32 x -> cvt fp16 -> STS (double buffered);
//            cp.async W_hi sub-tile (double buffered);
//            4 k16 MMA steps x 16 MMAs.
// SMEM: [0,512) bias; A bufs 2x16K; B bufs 2x16K  -> 66048 B total.
// ---------------------------------------------------------------------------
#define SM_BIAS 0
#define SM_A 512
#define SM_B (512 + 2 * 16384)
#define SMEM_BYTES (512 + 2 * 16384 + 2 * 16384)

__global__ void __launch_bounds__(256, 2) gemm_kernel(const float* __restrict__ x,
                                                      const float* __restrict__ bout,
                                                      float* __restrict__ out) {
    extern __shared__ char smem[];
    const uint32_t sb = smem_u32(smem);
    const int tid = threadIdx.x;
    const int lane = tid & 31;
    const int wid = tid >> 5;
    const int warp_m = wid >> 1;       // 0..3
    const int warp_n = wid & 1;        // 0..1
    const int m_blk = blockIdx.x >> 2, n_blk = blockIdx.x & 3;
    const int m_base = m_blk * TM, n_base = n_blk * TN;

    if (tid < TN) reinterpret_cast<float*>(smem + SM_BIAS)[tid] = bout[n_base + tid];

    const float* gx = x + (size_t)m_base * KK;

    // ---- load one 128x64 fp32 x chunk into regs (8 float4 / thread) ----
    uint4 xr[8];
    auto ldx = [&](int kb) {
#pragma unroll
        for (int r = 0; r < 8; ++r) {
            int idx = tid + (r << 8);
            int row = idx >> 4, c4 = idx & 15;
            xr[r] = *reinterpret_cast<const uint4*>(gx + (size_t)row * KK + kb * 64 + c4 * 4);
        }
    };
    // ---- convert + store chunk into A buffer s ----
    auto stsA = [&](int s) {
        const uint32_t sa = sb + SM_A + s * 16384;
#pragma unroll
        for (int r = 0; r < 8; ++r) {
            int idx = tid + (r << 8);
            int row = idx >> 4, c4 = idx & 15;
            __half2 h0 = __floats2half2_rn(__uint_as_float(xr[r].x), __uint_as_float(xr[r].y));
            __half2 h1 = __floats2half2_rn(__uint_as_float(xr[r].z), __uint_as_float(xr[r].w));
            uint32_t u0 = *reinterpret_cast<uint32_t*>(&h0);
            uint32_t u1 = *reinterpret_cast<uint32_t*>(&h1);
            uint32_t off = sw128((uint32_t)(row * 128 + c4 * 8));
            asm volatile("st.shared.v2.b32 [%0], {%1,%2};"
                         :: "r"(sa + off), "r"(u0), "r"(u1) : "memory");
        }
    };
    // ---- cp.async W_hi sub-tile for chunk kb into B buffer kb&1 ----
    auto prefB = [&](int kb) {
        const uint32_t sbb = sb + SM_B + (kb & 1) * 16384;
#pragma unroll
        for (int r = 0; r < 4; ++r) {
            int idx = tid + (r << 8);                // 0..1023
            int row = idx >> 3, c16 = idx & 7;
            uint32_t sw = sw128((uint32_t)(row * 128 + c16 * 16));
            cp16(sbb + sw, g_B + (size_t)(n_base + row) * KK + kb * 64 + c16 * 8);
        }
    };

    ldx(0);
    prefB(0); cp_commit();
    prefB(1); cp_commit();

    float c[2][8][4];
#pragma unroll
    for (int mi = 0; mi < 2; ++mi)
#pragma unroll
        for (int ni = 0; ni < 8; ++ni)
#pragma unroll
            for (int q = 0; q < 4; ++q) c[mi][ni][q] = 0.f;

    for (int kb = 0; kb < 8; ++kb) {
        stsA(kb & 1);                 // bufA[kb&1]; last read at chunk kb-2, fenced by kb-1's sync
        cp_wait1();                   // B chunk kb resident
        __syncthreads();
        if (kb < 7) ldx(kb + 1);      // overlap next x load with MMA

        const uint32_t sa  = sb + SM_A + (kb & 1) * 16384;
        const uint32_t sbb = sb + SM_B + (kb & 1) * 16384;
#pragma unroll
        for (int s = 0; s < 4; ++s) {                // k16 steps
            uint32_t a[2][4];
#pragma unroll
            for (int mi = 0; mi < 2; ++mi) {
                int row = warp_m * 32 + mi * 16 + (lane & 15);
                int kbyte = s * 32 + ((lane >> 4) << 4);
                ldsm_x4(a[mi], sa + sw128((uint32_t)(row * 128 + kbyte)));
            }
#pragma unroll
            for (int p = 0; p < 4; ++p) {            // n8 tile pairs
                uint32_t b[4];
                int nrow = warp_n * 64 + p * 16 + ((lane >> 4) * 8 + (lane & 7));
                int kbyte = s * 32 + (((lane >> 3) & 1) << 4);
                ldsm_x4(b, sbb + sw128((uint32_t)(nrow * 128 + kbyte)));
                mma16816(c[0][2 * p],     a[0], b[0], b[1]);
                mma16816(c[0][2 * p + 1], a[0], b[2], b[3]);
                mma16816(c[1][2 * p],     a[1], b[0], b[1]);
                mma16816(c[1][2 * p + 1], a[1], b[2], b[3]);
            }
        }
        __syncthreads();
        if (kb < 6) prefB(kb + 2);
        cp_commit();                  // empty groups near tail keep wait counts valid
    }

    // ---- epilogue: + bias, fp32 stores ----
    const float* bias = reinterpret_cast<const float*>(smem + SM_BIAS);
#pragma unroll
    for (int mi = 0; mi < 2; ++mi) {
        int gm0 = m_base + warp_m * 32 + mi * 16 + (lane >> 2);
#pragma unroll
        for (int ni = 0; ni < 8; ++ni) {
            int cn = warp_n * 64 + ni * 8 + ((lane & 3) << 1);
            int gn = n_base + cn;
            float b0 = bias[cn], b1 = bias[cn + 1];
            float2 v0 = make_float2(c[mi][ni][0] + b0, c[mi][ni][1] + b1);
            float2 v1 = make_float2(c[mi][ni][2] + b0, c[mi][ni][3] + b1);
            *reinterpret_cast<float2*>(out + (size_t)gm0 * NN + gn)       = v0;
            *reinterpret_cast<float2*>(out + (size_t)(gm0 + 8) * NN + gn) = v1;
        }
    }
}

// ---------------------------------------------------------------------------
// kernel_launch
// inputs: 0=x (fp32 4*2048*512), 1=attn_mask (dead), 2=Wqkv (dead),
//         3=bqkv (dead), 4=Wout (fp32 512*512), 5=bout (fp32 512)
// ---------------------------------------------------------------------------
extern "C" void kernel_launch(void* const* d_in, const int* in_sizes, int n_in,
                              void* d_out, int out_size) {
    const float* x    = (const float*)d_in[0];
    const float* Wout = (const float*)d_in[4];
    const float* bo   = (const float*)d_in[5];
    float* out = (float*)d_out;

    cudaFuncSetAttribute(gemm_kernel, cudaFuncAttributeMaxDynamicSharedMemorySize, SMEM_BYTES);

    prep_w<<<(NN * KK / 4) / 256, 256>>>(Wout);
    gemm_kernel<<<(MM / TM) * (NN / TN), 256, SMEM_BYTES>>>(x, bo, out);
}

// round 7
// speedup vs baseline: 1.9909x; 1.1606x over previous
#include <cuda_runtime.h>
#include <cuda_fp16.h>
#include <cstdint>

// Live computation: out[B*S, E] = x @ Wout + bout  (attention in reference is dead code)
// M=8192, N=512, K=512, fp32 in/out.
// Single-term fp16 GEMM: out = fp16(x) @ fp16(W) + bias (fp32 accum).
// Measured (R6): rel_err 2.93e-4 << 1e-3 gate.
#define MM 8192
#define NN 512
#define KK 512
#define TM 128
#define TN 128

// fp16 operands (device globals: allocation-free contract)
__device__ __align__(16) __half g_A[(size_t)MM * KK];   // 8 MB, m-major
__device__ __align__(16) __half g_B[(size_t)NN * KK];   // 0.5 MB, n-major (W transposed)

// ---------------------------------------------------------------------------
// Helpers (baseline sm_100: cp.async / ldmatrix / mma.sync)
// ---------------------------------------------------------------------------
__device__ __forceinline__ uint32_t smem_u32(const void* p) {
    uint32_t r;
    asm("{ .reg .u64 t; cvta.to.shared.u64 t, %1; cvt.u32.u64 %0, t; }" : "=r"(r) : "l"(p));
    return r;
}
__device__ __forceinline__ uint32_t sw128(uint32_t off) { return off ^ ((off >> 3) & 0x70); }

__device__ __forceinline__ void cp16(uint32_t dst, const void* src) {
    asm volatile("cp.async.cg.shared.global [%0], [%1], 16;" :: "r"(dst), "l"(src) : "memory");
}
__device__ __forceinline__ void cp_commit() {
    asm volatile("cp.async.commit_group;" ::: "memory");
}
__device__ __forceinline__ void cp_wait1() {
    asm volatile("cp.async.wait_group 1;" ::: "memory");
}
__device__ __forceinline__ void ldsm_x4(uint32_t* r, uint32_t addr) {
    asm volatile("ldmatrix.sync.aligned.m8n8.x4.shared.b16 {%0,%1,%2,%3}, [%4];"
                 : "=r"(r[0]), "=r"(r[1]), "=r"(r[2]), "=r"(r[3]) : "r"(addr));
}
__device__ __forceinline__ void mma16816(float* c, const uint32_t* a, uint32_t b0, uint32_t b1) {
    asm volatile(
        "mma.sync.aligned.m16n8k16.row.col.f32.f16.f16.f32 "
        "{%0,%1,%2,%3}, {%4,%5,%6,%7}, {%8,%9}, {%0,%1,%2,%3};"
        : "+f"(c[0]), "+f"(c[1]), "+f"(c[2]), "+f"(c[3])
        : "r"(a[0]), "r"(a[1]), "r"(a[2]), "r"(a[3]), "r"(b0), "r"(b1));
}

// ---------------------------------------------------------------------------
// Fused prep: blocks [0,2048) convert x -> g_A (8 floats/thread, streaming);
//             blocks [2048,2304) convert+transpose Wout -> g_B.
// ---------------------------------------------------------------------------
#define XBLOCKS 2048
__global__ void __launch_bounds__(256) prep(const float* __restrict__ x,
                                            const float* __restrict__ W) {
    int b = blockIdx.x;
    if (b < XBLOCKS) {
        int idx = b * 256 + threadIdx.x;             // over float8: MM*KK/8
        const float4* src = reinterpret_cast<const float4*>(x) + (size_t)idx * 2;
        float4 v0 = src[0], v1 = src[1];
        __half2 h0 = __floats2half2_rn(v0.x, v0.y);
        __half2 h1 = __floats2half2_rn(v0.z, v0.w);
        __half2 h2 = __floats2half2_rn(v1.x, v1.y);
        __half2 h3 = __floats2half2_rn(v1.z, v1.w);
        uint4 o;
        o.x = *reinterpret_cast<uint32_t*>(&h0);
        o.y = *reinterpret_cast<uint32_t*>(&h1);
        o.z = *reinterpret_cast<uint32_t*>(&h2);
        o.w = *reinterpret_cast<uint32_t*>(&h3);
        *reinterpret_cast<uint4*>(&g_A[(size_t)idx * 8]) = o;
    } else {
        int idx = (b - XBLOCKS) * 256 + threadIdx.x; // over NN*KK/4
        int n = idx >> 7;
        int k = (idx & 127) << 2;
        __half h[4];
#pragma unroll
        for (int i = 0; i < 4; ++i)
            h[i] = __float2half_rn(W[(size_t)(k + i) * NN + n]);
        uint2 u;
        u.x = (uint32_t)__half_as_ushort(h[0]) | ((uint32_t)__half_as_ushort(h[1]) << 16);
        u.y = (uint32_t)__half_as_ushort(h[2]) | ((uint32_t)__half_as_ushort(h[3]) << 16);
        *reinterpret_cast<uint2*>(&g_B[(size_t)n * KK + k]) = u;
    }
}

// ---------------------------------------------------------------------------
// GEMM: 128x128 CTA tile, 8 warps (4m x 2n), 8 k64 chunks.
// Both operands via cp.async, 3-stage single-sync-per-chunk pipeline.
// SMEM: [0,512) bias; then 3 stages x (A 16K + B 16K) = 98816 B.
// ---------------------------------------------------------------------------
#define SM_BIAS 0
#define SM_T 512
#define STAGE_BYTES 32768
#define SMEM_BYTES (512 + 3 * STAGE_BYTES)

__global__ void __launch_bounds__(256, 2) gemm_kernel(const float* __restrict__ bout,
                                                      float* __restrict__ out) {
    extern __shared__ char smem[];
    const uint32_t sb = smem_u32(smem);
    const int tid = threadIdx.x;
    const int lane = tid & 31;
    const int wid = tid >> 5;
    const int warp_m = wid >> 1;       // 0..3
    const int warp_n = wid & 1;        // 0..1
    const int m_blk = blockIdx.x >> 2, n_blk = blockIdx.x & 3;
    const int m_base = m_blk * TM, n_base = n_blk * TN;

    if (tid < TN) reinterpret_cast<float*>(smem + SM_BIAS)[tid] = bout[n_base + tid];

    // per-thread cp.async coordinates: 1024 (row,c16) pairs over 4 iterations
    const int prow = tid >> 1;                       // with r-offset below
    (void)prow;

    auto pref = [&](int kb) {
        const uint32_t st = sb + SM_T + (kb % 3) * STAGE_BYTES;
#pragma unroll
        for (int r = 0; r < 4; ++r) {
            int idx = tid + (r << 8);                // 0..1023
            int row = idx >> 3, c16 = idx & 7;
            uint32_t sw = sw128((uint32_t)(row * 128 + c16 * 16));
            cp16(st + sw,         g_A + (size_t)(m_base + row) * KK + kb * 64 + c16 * 8);
            cp16(st + 16384 + sw, g_B + (size_t)(n_base + row) * KK + kb * 64 + c16 * 8);
        }
    };

    pref(0); cp_commit();
    pref(1); cp_commit();

    float c[2][8][4];
#pragma unroll
    for (int mi = 0; mi < 2; ++mi)
#pragma unroll
        for (int ni = 0; ni < 8; ++ni)
#pragma unroll
            for (int q = 0; q < 4; ++q) c[mi][ni][q] = 0.f;

    for (int kb = 0; kb < 8; ++kb) {
        cp_wait1();                   // chunk kb resident (kb+1 may still be in flight)
        __syncthreads();              // all warps done reading slot (kb+2)%3 == (kb-1)%3
        if (kb < 6) pref(kb + 2);     // fill the just-freed slot, overlaps MMA below
        cp_commit();                  // (empty group near tail keeps wait counts valid)

        const uint32_t sa  = sb + SM_T + (kb % 3) * STAGE_BYTES;
        const uint32_t sbb = sa + 16384;
#pragma unroll
        for (int s = 0; s < 4; ++s) {                // k16 steps
            uint32_t a[2][4];
#pragma unroll
            for (int mi = 0; mi < 2; ++mi) {
                int row = warp_m * 32 + mi * 16 + (lane & 15);
                int kbyte = s * 32 + ((lane >> 4) << 4);
                ldsm_x4(a[mi], sa + sw128((uint32_t)(row * 128 + kbyte)));
            }
#pragma unroll
            for (int p = 0; p < 4; ++p) {            // n8 tile pairs
                uint32_t b[4];
                int nrow = warp_n * 64 + p * 16 + ((lane >> 4) * 8 + (lane & 7));
                int kbyte = s * 32 + (((lane >> 3) & 1) << 4);
                ldsm_x4(b, sbb + sw128((uint32_t)(nrow * 128 + kbyte)));
                mma16816(c[0][2 * p],     a[0], b[0], b[1]);
                mma16816(c[0][2 * p + 1], a[0], b[2], b[3]);
                mma16816(c[1][2 * p],     a[1], b[0], b[1]);
                mma16816(c[1][2 * p + 1], a[1], b[2], b[3]);
            }
        }
    }

    // ---- epilogue: + bias, fp32 stores ----
    const float* bias = reinterpret_cast<const float*>(smem + SM_BIAS);
#pragma unroll
    for (int mi = 0; mi < 2; ++mi) {
        int gm0 = m_base + warp_m * 32 + mi * 16 + (lane >> 2);
#pragma unroll
        for (int ni = 0; ni < 8; ++ni) {
            int cn = warp_n * 64 + ni * 8 + ((lane & 3) << 1);
            int gn = n_base + cn;
            float b0 = bias[cn], b1 = bias[cn + 1];
            float2 v0 = make_float2(c[mi][ni][0] + b0, c[mi][ni][1] + b1);
            float2 v1 = make_float2(c[mi][ni][2] + b0, c[mi][ni][3] + b1);
            *reinterpret_cast<float2*>(out + (size_t)gm0 * NN + gn)       = v0;
            *reinterpret_cast<float2*>(out + (size_t)(gm0 + 8) * NN + gn) = v1;
        }
    }
}

// ---------------------------------------------------------------------------
// kernel_launch
// inputs: 0=x (fp32 4*2048*512), 1=attn_mask (dead), 2=Wqkv (dead),
//         3=bqkv (dead), 4=Wout (fp32 512*512), 5=bout (fp32 512)
// ---------------------------------------------------------------------------
extern "C" void kernel_launch(void* const* d_in, const int* in_sizes, int n_in,
                              void* d_out, int out_size) {
    const float* x    = (const float*)d_in[0];
    const float* Wout = (const float*)d_in[4];
    const float* bo   = (const float*)d_in[5];
    float* out = (float*)d_out;

    cudaFuncSetAttribute(gemm_kernel, cudaFuncAttributeMaxDynamicSharedMemorySize, SMEM_BYTES);

    prep<<<XBLOCKS + (NN * KK / 4) / 256, 256>>>(x, Wout);
    gemm_kernel<<<(MM / TM) * (NN / TN), 256, SMEM_BYTES>>>(bo, out);
}